// round 15
// baseline (speedup 1.0000x reference)
#include <cuda_runtime.h>
#include <cuda_bf16.h>
#include <cstdint>

#define NT 128            // 4 warps, 64 voxels per block
#define TS 24

// weights as bf16 B-frags, layout [tile(24)][lane(32)][kt2(4)] uint2
__device__ uint32_t g_whF[4 * 6144];
__device__ uint32_t g_wiF[3 * 6144];
// inter-layer h/x as bf16 A-frags: [t][mtile(1024)][kt2(4)][lane(32)] uint4 = 50 MB
__device__ uint4 g_actb[TS * 1024 * 4 * 32];

// ---- smem float offsets ----
#define S_SEL  0        // 4096: sel[j][v] accumulator (written during layer 3)
#define S_SELB 4096     // 4096: head ping-pong
#define S_WST  8192     // 4096: head fcW staging
#define S_VIN  12288    // 1536: vin[t][v]  (only read in layer 0)
#define S_BS   13824    // 4 x 256 fused biases
#define S_W0   14848    // 192 layer-0 rank-1 ih weights
#define SMEM_FLOATS 15040   // 60,160 B

static __device__ __forceinline__ uint32_t pkbf(float lo, float hi) {
    __nv_bfloat162 b = __float22bfloat162_rn(make_float2(lo, hi));
    return *(uint32_t*)&b;
}
static __device__ __forceinline__ float tanha(float x) {
    float y; asm("tanh.approx.f32 %0, %1;" : "=f"(y) : "f"(x)); return y;
}
static __device__ __forceinline__ float sigt(float x) {
    return fmaf(tanha(0.5f * x), 0.5f, 0.5f);
}
#define MMAB(c, a, bx, by) asm volatile( \
    "mma.sync.aligned.m16n8k16.row.col.f32.bf16.bf16.f32 " \
    "{%0,%1,%2,%3},{%4,%5,%6,%7},{%8,%9},{%0,%1,%2,%3};" \
    : "+f"((c)[0]), "+f"((c)[1]), "+f"((c)[2]), "+f"((c)[3]) \
    : "r"((a).x), "r"((a).y), "r"((a).z), "r"((a).w), "r"(bx), "r"(by))

// ---- prep: convert GRU weights to bf16 B-frag globals, [tile][lane][kt2] ----
__global__ void __launch_bounds__(512)
prep_kernel(const float* __restrict__ wih0, const float* __restrict__ whh0,
            const float* __restrict__ wihL, const float* __restrict__ whhL)
{
    int idx = blockIdx.x * 512 + threadIdx.x;
    if (idx >= 43008) return;
    const float* W;
    uint32_t* dst;
    int i;
    if (idx < 24576) {
        int l = idx / 6144; i = idx % 6144;
        W = (l == 0) ? whh0 : whhL + (l - 1) * 12288;
        dst = g_whF + l * 6144;
    } else {
        int r = idx - 24576;
        int l = r / 6144; i = r % 6144;
        W = wihL + l * 12288;
        dst = g_wiF + l * 6144;
    }
    // dst u32 index i: br=i&1, kt2=(i>>1)&3, ln=(i>>3)&31, gt=i>>8
    int br = i & 1, kt2 = (i >> 1) & 3, ln = (i >> 3) & 31, gt = i >> 8;
    int g = gt * 8 + (ln >> 2);
    int k = kt2 * 16 + (ln & 3) * 2 + br * 8;
    dst[i] = pkbf(W[g * 64 + k], W[g * 64 + k + 1]);
}

// One GRU layer, 24 steps, fully warp-autonomous (no barriers).
// Warp owns 16 voxels (m-tile mt) x all 192 gates. h carried fp32 in regs;
// h_new C-frags repack thread-locally into next step's A-frags.
template<bool L0, bool LAST>
static __device__ void layer_run(float* __restrict__ sm, int lane, int w, int mt,
                                 const uint4* __restrict__ WH4,
                                 const uint4* __restrict__ WI4,
                                 const float* __restrict__ BS,
                                 int t1, int t2)
{
    const int gq = lane >> 2, cc = lane & 3;
    float hp[32];                 // fp32 h carry, [jt][q]
    #pragma unroll
    for (int i = 0; i < 32; ++i) hp[i] = 0.f;
    uint4 ah[4];                  // current h A-frags (bf16)

    for (int t = 0; t < TS; ++t) {
        uint4 ax[4];
        if (!L0) {
            #pragma unroll
            for (int kt2 = 0; kt2 < 4; ++kt2)
                ax[kt2] = g_actb[((size_t)(t * 1024 + mt) * 4 + kt2) * 32 + lane];
        }

        #pragma unroll
        for (int jt = 0; jt < 8; ++jt) {
            float cr[4]  = {0.f, 0.f, 0.f, 0.f};
            float cz[4]  = {0.f, 0.f, 0.f, 0.f};
            float cnh[4] = {0.f, 0.f, 0.f, 0.f};
            float cnx[4] = {0.f, 0.f, 0.f, 0.f};

            if (t > 0) {
                uint4 br0 = WH4[((jt)      * 32 + lane) * 2 + 0];
                uint4 br1 = WH4[((jt)      * 32 + lane) * 2 + 1];
                uint4 bz0 = WH4[((8 + jt)  * 32 + lane) * 2 + 0];
                uint4 bz1 = WH4[((8 + jt)  * 32 + lane) * 2 + 1];
                uint4 bn0 = WH4[((16 + jt) * 32 + lane) * 2 + 0];
                uint4 bn1 = WH4[((16 + jt) * 32 + lane) * 2 + 1];
                MMAB(cr,  ah[0], br0.x, br0.y); MMAB(cr,  ah[1], br0.z, br0.w);
                MMAB(cr,  ah[2], br1.x, br1.y); MMAB(cr,  ah[3], br1.z, br1.w);
                MMAB(cz,  ah[0], bz0.x, bz0.y); MMAB(cz,  ah[1], bz0.z, bz0.w);
                MMAB(cz,  ah[2], bz1.x, bz1.y); MMAB(cz,  ah[3], bz1.z, bz1.w);
                MMAB(cnh, ah[0], bn0.x, bn0.y); MMAB(cnh, ah[1], bn0.z, bn0.w);
                MMAB(cnh, ah[2], bn1.x, bn1.y); MMAB(cnh, ah[3], bn1.z, bn1.w);
            }
            if (!L0) {
                uint4 br0 = WI4[((jt)      * 32 + lane) * 2 + 0];
                uint4 br1 = WI4[((jt)      * 32 + lane) * 2 + 1];
                uint4 bz0 = WI4[((8 + jt)  * 32 + lane) * 2 + 0];
                uint4 bz1 = WI4[((8 + jt)  * 32 + lane) * 2 + 1];
                uint4 bn0 = WI4[((16 + jt) * 32 + lane) * 2 + 0];
                uint4 bn1 = WI4[((16 + jt) * 32 + lane) * 2 + 1];
                MMAB(cr,  ax[0], br0.x, br0.y); MMAB(cr,  ax[1], br0.z, br0.w);
                MMAB(cr,  ax[2], br1.x, br1.y); MMAB(cr,  ax[3], br1.z, br1.w);
                MMAB(cz,  ax[0], bz0.x, bz0.y); MMAB(cz,  ax[1], bz0.z, bz0.w);
                MMAB(cz,  ax[2], bz1.x, bz1.y); MMAB(cz,  ax[3], bz1.z, bz1.w);
                MMAB(cnx, ax[0], bn0.x, bn0.y); MMAB(cnx, ax[1], bn0.z, bn0.w);
                MMAB(cnx, ax[2], bn1.x, bn1.y); MMAB(cnx, ax[3], bn1.z, bn1.w);
            }

            // thread-local combine
            #pragma unroll
            for (int q = 0; q < 4; ++q) {
                int j = 8 * jt + 2 * cc + (q & 1);
                int vloc = w * 16 + gq + 8 * (q >> 1);
                float xr = 0.f, xz = 0.f, xn;
                if (L0) {
                    float xv = sm[S_VIN + t * 64 + vloc];
                    xr = xv * sm[S_W0 + j];
                    xz = xv * sm[S_W0 + 64 + j];
                    xn = xv * sm[S_W0 + 128 + j] + BS[192 + j];
                } else {
                    xn = cnx[q] + BS[192 + j];
                }
                float r  = sigt(cr[q] + xr + BS[j]);
                float z  = sigt(cz[q] + xz + BS[64 + j]);
                float nn = tanha(xn + r * (cnh[q] + BS[128 + j]));
                float hnv = (1.f - z) * nn + z * hp[jt * 4 + q];
                hp[jt * 4 + q] = hnv;
                if (LAST) {
                    if (t == t2)      sm[S_SEL + j * 64 + vloc]  = hnv;
                    else if (t == t1) sm[S_SEL + j * 64 + vloc] += hnv;
                }
            }
        }

        // repack fp32 carry -> bf16 A-frags for next step (pure registers)
        #pragma unroll
        for (int kt2 = 0; kt2 < 4; ++kt2) {
            ah[kt2] = make_uint4(
                pkbf(hp[(2 * kt2)     * 4 + 0], hp[(2 * kt2)     * 4 + 1]),
                pkbf(hp[(2 * kt2)     * 4 + 2], hp[(2 * kt2)     * 4 + 3]),
                pkbf(hp[(2 * kt2 + 1) * 4 + 0], hp[(2 * kt2 + 1) * 4 + 1]),
                pkbf(hp[(2 * kt2 + 1) * 4 + 2], hp[(2 * kt2 + 1) * 4 + 3]));
        }
        if (!LAST) {   // h output = next layer's x (thread-private addresses)
            #pragma unroll
            for (int kt2 = 0; kt2 < 4; ++kt2)
                g_actb[((size_t)(t * 1024 + mt) * 4 + kt2) * 32 + lane] = ah[kt2];
        }
    }
}

__global__ void __launch_bounds__(NT)
fused_rnn_kernel(const float* __restrict__ x,   const int*   __restrict__ lengths,
                 const float* __restrict__ sf,  const float* __restrict__ bp,
                 const float* __restrict__ wih0,const float* __restrict__ whh0,
                 const float* __restrict__ bih0,const float* __restrict__ bhh0,
                 const float* __restrict__ wihL,const float* __restrict__ whhL,
                 const float* __restrict__ bihL,const float* __restrict__ bhhL,
                 const float* __restrict__ bng, const float* __restrict__ bnb,
                 const float* __restrict__ bnm, const float* __restrict__ bnv,
                 const float* __restrict__ fcW, const float* __restrict__ fcb,
                 const float* __restrict__ fcWo,const float* __restrict__ fcbo,
                 float* __restrict__ out)
{
    extern __shared__ float sm[];
    const int tid = threadIdx.x;
    const int lane = tid & 31, w = tid >> 5;
    const int blk = blockIdx.x;
    const int vbase = blk * 64;
    const int n  = vbase >> 12;
    const int sb = vbase & 4095;
    const int mt = blk * 4 + w;

    // ---- staging (biases, rank-1 W0, vin) ----
    for (int l = 0; l < 4; ++l) {
        const float* Bi = (l == 0) ? bih0 : bihL + (l - 1) * 192;
        const float* Bh = (l == 0) ? bhh0 : bhhL + (l - 1) * 192;
        if (tid < 64) {
            int j = tid;
            sm[S_BS + l * 256 + j]       = Bi[j] + Bh[j];
            sm[S_BS + l * 256 + 64 + j]  = Bi[64 + j] + Bh[64 + j];
            sm[S_BS + l * 256 + 128 + j] = Bh[128 + j];
            sm[S_BS + l * 256 + 192 + j] = Bi[128 + j];
        }
    }
    if (tid < 64 + 128) { if (tid < 192) sm[S_W0 + tid] = wih0[tid]; }
    for (int idx = tid; idx < TS * 64; idx += NT) {   // vin[t][v]
        int t = idx >> 6, v = idx & 63;
        int p = t % 3;
        sm[S_VIN + idx] = x[n * 98304 + t * 4096 + sb + v] * sf[p] + bp[p];
    }
    __syncthreads();

    const int len = lengths[n];
    const int t1 = len - 1, t2 = len - 4;

    // ---- 4 layers, barrier-free recurrence ----
    layer_run<true , false>(sm, lane, w, mt, (const uint4*)g_whF,
                            (const uint4*)g_wiF, sm + S_BS, t1, t2);
    layer_run<false, false>(sm, lane, w, mt, (const uint4*)(g_whF + 6144),
                            (const uint4*)g_wiF, sm + S_BS + 256, t1, t2);
    layer_run<false, false>(sm, lane, w, mt, (const uint4*)(g_whF + 12288),
                            (const uint4*)(g_wiF + 6144), sm + S_BS + 512, t1, t2);
    layer_run<false, true >(sm, lane, w, mt, (const uint4*)(g_whF + 18432),
                            (const uint4*)(g_wiF + 12288), sm + S_BS + 768, t1, t2);
    __syncthreads();

    // ---- head: sel already in smem [j][v]; 5x (BN+SiLU+FC); BN+SiLU; out ----
    float* A = sm + S_SEL;    // [j][v] 64 x 64
    float* B = sm + S_SELB;
    float* WST = sm + S_WST;
    for (int i = 0; i < 5; ++i) {
        for (int idx = tid; idx < 4096; idx += NT) WST[idx] = fcW[i * 4096 + idx];
        #pragma unroll
        for (int it = 0; it < 32; ++it) {
            int idx = tid + it * NT, v = idx & 63, j = idx >> 6;
            float y = bng[i * 64 + j] * (A[j * 64 + v] - bnm[i * 64 + j])
                      * rsqrtf(bnv[i * 64 + j] + 1e-5f) + bnb[i * 64 + j];
            A[j * 64 + v] = y * sigt(y);
        }
        __syncthreads();
        #pragma unroll
        for (int it = 0; it < 32; ++it) {
            int idx = tid + it * NT, v = idx & 63, o = idx >> 6;
            float acc = fcb[i * 64 + o];
            #pragma unroll 8
            for (int j = 0; j < 64; ++j) acc += A[j * 64 + v] * WST[o * 64 + j];
            B[o * 64 + v] = acc;
        }
        __syncthreads();
        float* tswp = A; A = B; B = tswp;
    }
    #pragma unroll
    for (int it = 0; it < 32; ++it) {
        int idx = tid + it * NT, v = idx & 63, j = idx >> 6;
        float y = bng[5 * 64 + j] * (A[j * 64 + v] - bnm[5 * 64 + j])
                  * rsqrtf(bnv[5 * 64 + j] + 1e-5f) + bnb[5 * 64 + j];
        A[j * 64 + v] = y * sigt(y);
    }
    __syncthreads();
    if (tid < 64) {
        float acc = fcbo[0];
        #pragma unroll 8
        for (int j = 0; j < 64; ++j) acc += A[j * 64 + tid] * fcWo[j];
        out[vbase + tid] = acc;
    }
}

extern "C" void kernel_launch(void* const* d_in, const int* in_sizes, int n_in,
                              void* d_out, int out_size)
{
    const float* x     = (const float*)d_in[0];
    const int*   lens  = (const int*)  d_in[1];
    const float* sf    = (const float*)d_in[2];
    const float* bp    = (const float*)d_in[3];
    const float* wih0  = (const float*)d_in[4];
    const float* whh0  = (const float*)d_in[5];
    const float* bih0  = (const float*)d_in[6];
    const float* bhh0  = (const float*)d_in[7];
    const float* wihL  = (const float*)d_in[8];
    const float* whhL  = (const float*)d_in[9];
    const float* bihL  = (const float*)d_in[10];
    const float* bhhL  = (const float*)d_in[11];
    const float* bng   = (const float*)d_in[12];
    const float* bnb   = (const float*)d_in[13];
    const float* bnm   = (const float*)d_in[14];
    const float* bnv   = (const float*)d_in[15];
    const float* fcW   = (const float*)d_in[16];
    const float* fcb   = (const float*)d_in[17];
    const float* fcWo  = (const float*)d_in[18];
    const float* fcbo  = (const float*)d_in[19];
    float* out = (float*)d_out;

    prep_kernel<<<84, 512>>>(wih0, whh0, wihL, whhL);

    const size_t smem = SMEM_FLOATS * sizeof(float);   // 60,160 B
    cudaFuncSetAttribute(fused_rnn_kernel,
                         cudaFuncAttributeMaxDynamicSharedMemorySize, (int)smem);
    fused_rnn_kernel<<<256, NT, smem>>>(
        x, lens, sf, bp, wih0, whh0, bih0, bhh0,
        wihL, whhL, bihL, bhhL, bng, bnb, bnm, bnv,
        fcW, fcb, fcWo, fcbo, out);
}

// round 16
// speedup vs baseline: 1.6819x; 1.6819x over previous
#include <cuda_runtime.h>
#include <cuda_bf16.h>
#include <cstdint>

#define NT 512
#define VB 128
#define TS 24

// layers 0-2 activations as bf16 A-frag tiles: [t][blk][1024 x uint4] = 50 MB
__device__ uint4 g_actb[TS * 128 * 1024];
// layer-3 output fp32, head layout [t][j][v_global] = 100 MB
__device__ float g_act2[TS * 64 * 16384];

// ---- smem float offsets ----
// weights: L0 WH @0 (6144); L1 WH@6144 WI@12288; L2 WH@18432 WI@24576; L3 WH@30720 WI@36864
#define S_H0  43008   // 4096 u32: h A-frags buf0 (regions disjoint per mg-group)
#define S_H1  47104
#define S_BS  51200   // 4 x 256 fused biases
#define S_W0  52224   // 192 layer-0 rank-1 ih weights
#define S_VIN 52416   // 3072 vin[t][v]
#define SMEM_FLOATS 55488   // 221,952 B

static __device__ __forceinline__ uint32_t pkbf(float lo, float hi) {
    __nv_bfloat162 b = __float22bfloat162_rn(make_float2(lo, hi));
    return *(uint32_t*)&b;
}
static __device__ __forceinline__ float tanha(float x) {
    float y; asm("tanh.approx.f32 %0, %1;" : "=f"(y) : "f"(x)); return y;
}
static __device__ __forceinline__ float sigt(float x) {
    return fmaf(tanha(0.5f * x), 0.5f, 0.5f);
}
#define MMAB(c, a, b) asm volatile( \
    "mma.sync.aligned.m16n8k16.row.col.f32.bf16.bf16.f32 " \
    "{%0,%1,%2,%3},{%4,%5,%6,%7},{%8,%9},{%0,%1,%2,%3};" \
    : "+f"((c)[0]), "+f"((c)[1]), "+f"((c)[2]), "+f"((c)[3]) \
    : "r"((a).x), "r"((a).y), "r"((a).z), "r"((a).w), "r"((b).x), "r"((b).y))
#define GROUP_BAR(mg) asm volatile("bar.sync %0, %1;" :: "r"(1 + (mg)), "r"(128) : "memory")

// One GRU layer, 24 steps, executed by free-running 128-thread mg-groups.
// KEY FIX vs R10: mg = w>>2 (group = warps {4mg..4mg+3}, one per SMSP) so each
// SMSP hosts 4 warps from 4 DIFFERENT free-running chains -> pipes overlap.
template<bool L0, bool LAST>
static __device__ void layer_run(float* __restrict__ sm, int tid, int blk,
                                 int whO, int wiO, int bsO)
{
    const int lane = tid & 31, w = tid >> 5;
    const int mg = w >> 2, ng = w & 3;           // <-- the one-line structural fix
    const int gq = lane >> 2, cc = lane & 3;
    const int vbase = blk * VB;
    const uint2* WHu = (const uint2*)(sm + whO);
    const uint2* WIu = (const uint2*)(sm + wiO);
    const float* BS = sm + bsO;
    float hp[16];
    #pragma unroll
    for (int i = 0; i < 16; ++i) hp[i] = 0.f;

    for (int t = 0; t < TS; ++t) {
        uint4*       hb_n = (uint4*)(sm + ((t & 1) ? S_H0 : S_H1));
        const uint4* hb_c = (const uint4*)(sm + ((t & 1) ? S_H1 : S_H0));

        float cr[4][4], cz[4][4], cnh[4][4], cnx[4][4];
        #pragma unroll
        for (int f = 0; f < 4; ++f)
            #pragma unroll
            for (int q = 0; q < 4; ++q) {
                cr[f][q] = 0.f; cz[f][q] = 0.f; cnh[f][q] = 0.f; cnx[f][q] = 0.f;
            }

        // ---- pass 1: ih MMAs (no h dependency; x straight from global/L2) ----
        if (!L0) {
            const uint4* xs = &g_actb[(size_t)(t * 128 + blk) * 1024];
            #pragma unroll
            for (int kt2 = 0; kt2 < 4; ++kt2) {
                uint2 bi2[6];
                #pragma unroll
                for (int ji = 0; ji < 2; ++ji) {
                    int jt = 2 * ng + ji;
                    bi2[ji*3+0] = WIu[((jt)      * 4 + kt2) * 32 + lane];
                    bi2[ji*3+1] = WIu[((8 + jt)  * 4 + kt2) * 32 + lane];
                    bi2[ji*3+2] = WIu[((16 + jt) * 4 + kt2) * 32 + lane];
                }
                #pragma unroll
                for (int mi = 0; mi < 2; ++mi) {
                    uint4 ax = xs[((2 * mg + mi) * 4 + kt2) * 32 + lane];
                    #pragma unroll
                    for (int ji = 0; ji < 2; ++ji) {
                        int f = mi * 2 + ji;
                        MMAB(cr[f],  ax, bi2[ji*3+0]);
                        MMAB(cz[f],  ax, bi2[ji*3+1]);
                        MMAB(cnx[f], ax, bi2[ji*3+2]);
                    }
                }
            }
        }

        // ---- pass 2: hh MMAs (skipped entirely at t=0) ----
        if (t > 0) {
            #pragma unroll
            for (int kt2 = 0; kt2 < 4; ++kt2) {
                uint2 bh[6];
                #pragma unroll
                for (int ji = 0; ji < 2; ++ji) {
                    int jt = 2 * ng + ji;
                    bh[ji*3+0] = WHu[((jt)      * 4 + kt2) * 32 + lane];
                    bh[ji*3+1] = WHu[((8 + jt)  * 4 + kt2) * 32 + lane];
                    bh[ji*3+2] = WHu[((16 + jt) * 4 + kt2) * 32 + lane];
                }
                #pragma unroll
                for (int mi = 0; mi < 2; ++mi) {
                    uint4 ah = hb_c[((2 * mg + mi) * 4 + kt2) * 32 + lane];
                    #pragma unroll
                    for (int ji = 0; ji < 2; ++ji) {
                        int f = mi * 2 + ji;
                        MMAB(cr[f],  ah, bh[ji*3+0]);
                        MMAB(cz[f],  ah, bh[ji*3+1]);
                        MMAB(cnh[f], ah, bh[ji*3+2]);
                    }
                }
            }
        }

        // ---- thread-local combine; h packs straight into A-frag uint4 ----
        #pragma unroll
        for (int mi = 0; mi < 2; ++mi) {
            int mt = 2 * mg + mi;
            uint32_t rg[4];
            #pragma unroll
            for (int ji = 0; ji < 2; ++ji) {
                int f = mi * 2 + ji;
                float hv[4];
                #pragma unroll
                for (int q = 0; q < 4; ++q) {
                    int j = 16 * ng + 8 * ji + 2 * cc + (q & 1);
                    int v = mt * 16 + gq + 8 * (q >> 1);
                    float xr = 0.f, xz = 0.f, xn;
                    if (L0) {
                        float xv = sm[S_VIN + t * VB + v];
                        xr = xv * sm[S_W0 + j];
                        xz = xv * sm[S_W0 + 64 + j];
                        xn = xv * sm[S_W0 + 128 + j] + BS[192 + j];
                    } else {
                        xn = cnx[f][q] + BS[192 + j];
                    }
                    float r  = sigt(cr[f][q] + xr + BS[j]);
                    float z  = sigt(cz[f][q] + xz + BS[64 + j]);
                    float nn = tanha(xn + r * (cnh[f][q] + BS[128 + j]));
                    float hnv = (1.f - z) * nn + z * hp[f * 4 + q];
                    hp[f * 4 + q] = hnv;
                    hv[q] = hnv;
                    if (LAST)
                        g_act2[((size_t)(t * 64 + j) << 14) + vbase + v] = hnv;
                }
                rg[ji * 2 + 0] = pkbf(hv[0], hv[1]);
                rg[ji * 2 + 1] = pkbf(hv[2], hv[3]);
            }
            uint4 u = make_uint4(rg[0], rg[1], rg[2], rg[3]);
            hb_n[(mt * 4 + ng) * 32 + lane] = u;
            if (!LAST)
                g_actb[(size_t)(t * 128 + blk) * 1024 + (mt * 4 + ng) * 32 + lane] = u;
        }
        GROUP_BAR(mg);   // only this 128-thread group converges
    }
}

__global__ void __launch_bounds__(NT)
fused_rnn_kernel(const float* __restrict__ x,   const int*   __restrict__ lengths,
                 const float* __restrict__ sf,  const float* __restrict__ bp,
                 const float* __restrict__ wih0,const float* __restrict__ whh0,
                 const float* __restrict__ bih0,const float* __restrict__ bhh0,
                 const float* __restrict__ wihL,const float* __restrict__ whhL,
                 const float* __restrict__ bihL,const float* __restrict__ bhhL,
                 const float* __restrict__ bng, const float* __restrict__ bnb,
                 const float* __restrict__ bnm, const float* __restrict__ bnv,
                 const float* __restrict__ fcW, const float* __restrict__ fcb,
                 const float* __restrict__ fcWo,const float* __restrict__ fcbo,
                 float* __restrict__ out)
{
    extern __shared__ float sm[];
    const int tid = threadIdx.x;
    const int blk = blockIdx.x;
    const int vbase = blk * VB;
    const int n  = vbase >> 12;
    const int sb = vbase & 4095;

    // ---- stage ALL layers' weights + biases up front ----
    for (int l = 0; l < 4; ++l) {
        const float* Wh = (l == 0) ? whh0 : whhL + (l - 1) * 12288;
        const float* Wi = (l == 0) ? wih0 : wihL + (l - 1) * 12288;
        const float* Bi = (l == 0) ? bih0 : bihL + (l - 1) * 192;
        const float* Bh = (l == 0) ? bhh0 : bhhL + (l - 1) * 192;
        int whO = (l == 0) ? 0 : (6144 + (l - 1) * 12288);
        uint32_t* WHu = (uint32_t*)(sm + whO);
        uint32_t* WIu = WHu + 6144;
        for (int idx = tid; idx < 6144; idx += NT) {
            int gt = idx >> 8, kt2 = (idx >> 6) & 3, ln = (idx >> 1) & 31, br = idx & 1;
            int g = gt * 8 + (ln >> 2);
            int k = kt2 * 16 + (ln & 3) * 2 + br * 8;
            WHu[idx] = pkbf(Wh[g * 64 + k], Wh[g * 64 + k + 1]);
            if (l > 0) WIu[idx] = pkbf(Wi[g * 64 + k], Wi[g * 64 + k + 1]);
        }
        if (tid < 64) {
            int j = tid;
            sm[S_BS + l * 256 + j]       = Bi[j] + Bh[j];
            sm[S_BS + l * 256 + 64 + j]  = Bi[64 + j] + Bh[64 + j];
            sm[S_BS + l * 256 + 128 + j] = Bh[128 + j];
            sm[S_BS + l * 256 + 192 + j] = Bi[128 + j];
        }
    }
    if (tid < 192) sm[S_W0 + tid] = wih0[tid];
    for (int idx = tid; idx < TS * VB; idx += NT) {   // vin[t][v]
        int t = idx >> 7, v = idx & 127;
        int p = t % 3;
        sm[S_VIN + idx] = x[n * 98304 + t * 4096 + sb + v] * sf[p] + bp[p];
    }
    __syncthreads();

    // ---- four layers, mg-groups free-running throughout ----
    layer_run<true , false>(sm, tid, blk, 0,     0,     S_BS);
    layer_run<false, false>(sm, tid, blk, 6144,  12288, S_BS + 256);
    layer_run<false, false>(sm, tid, blk, 18432, 24576, S_BS + 512);
    layer_run<false, true >(sm, tid, blk, 30720, 36864, S_BS + 768);
    __syncthreads();

    // ---- head: sel = h[len-1]+h[len-4]; 5x (BN+SiLU+FC); BN+SiLU; out ----
    float* A = sm + S_H0;    // [j][v] 64 x 128 (spans H0+H1)
    float* B = sm;           // first 8192 floats of (now dead) weight region
    float* WST = sm + 8192;  // per-iteration fcW staging (4096)
    const int len = lengths[n];
    const int t1 = len - 1, t2 = len - 4;
    #pragma unroll
    for (int it = 0; it < 16; ++it) {
        int idx = tid + it * NT, v = idx & 127, j = idx >> 7;
        A[j * VB + v] = g_act2[((size_t)(t1 * 64 + j) << 14) + vbase + v]
                      + g_act2[((size_t)(t2 * 64 + j) << 14) + vbase + v];
    }
    __syncthreads();
    for (int i = 0; i < 5; ++i) {
        for (int idx = tid; idx < 4096; idx += NT) WST[idx] = fcW[i * 4096 + idx];
        #pragma unroll
        for (int it = 0; it < 16; ++it) {
            int idx = tid + it * NT, v = idx & 127, j = idx >> 7;
            float y = bng[i * 64 + j] * (A[j * VB + v] - bnm[i * 64 + j])
                      * rsqrtf(bnv[i * 64 + j] + 1e-5f) + bnb[i * 64 + j];
            A[j * VB + v] = y * sigt(y);
        }
        __syncthreads();
        #pragma unroll
        for (int it = 0; it < 16; ++it) {
            int idx = tid + it * NT, v = idx & 127, o = idx >> 7;
            float acc = fcb[i * 64 + o];
            #pragma unroll 8
            for (int j = 0; j < 64; ++j) acc += A[j * VB + v] * WST[o * 64 + j];
            B[o * VB + v] = acc;
        }
        __syncthreads();
        float* tswp = A; A = B; B = tswp;
    }
    #pragma unroll
    for (int it = 0; it < 16; ++it) {
        int idx = tid + it * NT, v = idx & 127, j = idx >> 7;
        float y = bng[5 * 64 + j] * (A[j * VB + v] - bnm[5 * 64 + j])
                  * rsqrtf(bnv[5 * 64 + j] + 1e-5f) + bnb[5 * 64 + j];
        A[j * VB + v] = y * sigt(y);
    }
    __syncthreads();
    if (tid < VB) {
        float acc = fcbo[0];
        #pragma unroll 8
        for (int j = 0; j < 64; ++j) acc += A[j * VB + tid] * fcWo[j];
        out[vbase + tid] = acc;
    }
}

extern "C" void kernel_launch(void* const* d_in, const int* in_sizes, int n_in,
                              void* d_out, int out_size)
{
    const float* x     = (const float*)d_in[0];
    const int*   lens  = (const int*)  d_in[1];
    const float* sf    = (const float*)d_in[2];
    const float* bp    = (const float*)d_in[3];
    const float* wih0  = (const float*)d_in[4];
    const float* whh0  = (const float*)d_in[5];
    const float* bih0  = (const float*)d_in[6];
    const float* bhh0  = (const float*)d_in[7];
    const float* wihL  = (const float*)d_in[8];
    const float* whhL  = (const float*)d_in[9];
    const float* bihL  = (const float*)d_in[10];
    const float* bhhL  = (const float*)d_in[11];
    const float* bng   = (const float*)d_in[12];
    const float* bnb   = (const float*)d_in[13];
    const float* bnm   = (const float*)d_in[14];
    const float* bnv   = (const float*)d_in[15];
    const float* fcW   = (const float*)d_in[16];
    const float* fcb   = (const float*)d_in[17];
    const float* fcWo  = (const float*)d_in[18];
    const float* fcbo  = (const float*)d_in[19];
    float* out = (float*)d_out;

    const size_t smem = SMEM_FLOATS * sizeof(float);   // 221,952 B
    cudaFuncSetAttribute(fused_rnn_kernel,
                         cudaFuncAttributeMaxDynamicSharedMemorySize, (int)smem);
    fused_rnn_kernel<<<128, NT, smem>>>(
        x, lens, sf, bp, wih0, whh0, bih0, bhh0,
        wihL, whhL, bihL, bhhL, bng, bnb, bnm, bnv,
        fcW, fcb, fcWo, fcbo, out);
}